// round 9
// baseline (speedup 1.0000x reference)
#include <cuda_runtime.h>

#define SEQ 1024
#define DKH 128
#define KIDX 5
#define QT 128
#define NTH 256
#define CHUNK 8
#define NCHUNK 16
#define SPITCH 132
#define TMASK (-80.0f)
#define SENT (-1.0e31f)
// smem: ssc 128*132 = 16896 | q 2*8*128 = 2048 | k 2*8*128 = 2048
#define SSC_FL   (QT * SPITCH)
#define QBUF_FL  (CHUNK * 128)
#define KBUF_FL  (CHUNK * 128)
#define SMEM_FLOATS (SSC_FL + 2 * QBUF_FL + 2 * KBUF_FL)
#define SMEMSZ (SMEM_FLOATS * 4)
#define VSUM_OFF 6144

typedef unsigned long long ull;

__device__ __forceinline__ ull pk2(float a, float b) {
    ull r;
    asm("mov.b64 %0, {%1, %2};" : "=l"(r) : "f"(a), "f"(b));
    return r;
}
__device__ __forceinline__ ull fma2v(ull a, ull b, ull c) {
    ull d;
    asm("fma.rn.f32x2 %0, %1, %2, %3;" : "=l"(d) : "l"(a), "l"(b), "l"(c));
    return d;
}
__device__ __forceinline__ ull add2v(ull a, ull b) {
    ull d;
    asm("add.rn.f32x2 %0, %1, %2;" : "=l"(d) : "l"(a), "l"(b));
    return d;
}

union U4 { float4 f; ull u[2]; };

// scalar 2^x (x in [-130, 0])
__device__ __forceinline__ float fexp2(float x) {
    float fz = x + 12582912.0f;
    float r  = x - (fz - 12582912.0f);
    float p  = 1.3333558e-3f;
    p = fmaf(p, r, 9.6181291e-3f);
    p = fmaf(p, r, 5.5504109e-2f);
    p = fmaf(p, r, 2.4022651e-1f);
    p = fmaf(p, r, 6.9314718e-1f);
    p = fmaf(p, r, 1.0f);
    return __int_as_float(__float_as_int(p) + (__float_as_int(fz) << 23));
}

// packed pair 2^x -> two scalars (bit-identical per lane to fexp2)
#define PEXP2(t2, negm2, r0, r1) do {                                   \
    ull x2_  = add2v((t2), (negm2));                                    \
    ull fz2_ = add2v(x2_, kMG);                                         \
    ull e2_  = add2v(fz2_, kNMG);                                       \
    ull r2_  = fma2v(e2_, kNEG1, x2_);                                  \
    ull p2_  = fma2v(kC5, r2_, kC4);                                    \
    p2_ = fma2v(p2_, r2_, kC3);                                         \
    p2_ = fma2v(p2_, r2_, kC2);                                         \
    p2_ = fma2v(p2_, r2_, kC1);                                         \
    p2_ = fma2v(p2_, r2_, kC0);                                         \
    unsigned fzl_, fzh_, pl_, ph_;                                      \
    asm("mov.b64 {%0,%1}, %2;" : "=r"(fzl_), "=r"(fzh_) : "l"(fz2_));   \
    asm("mov.b64 {%0,%1}, %2;" : "=r"(pl_), "=r"(ph_) : "l"(p2_));      \
    (r0) = __int_as_float((int)(pl_ + (fzl_ << 23)));                   \
    (r1) = __int_as_float((int)(ph_ + (fzh_ << 23)));                   \
} while (0)

__device__ __forceinline__ void ins5(float t, int idx, float tv[5], int ti[5]) {
    if (t > tv[4]) {
        tv[4] = t; ti[4] = idx;
        #pragma unroll
        for (int s = 4; s > 0; s--) {
            if (tv[s] > tv[s-1]) {
                float a = tv[s]; tv[s] = tv[s-1]; tv[s-1] = a;
                int   b = ti[s]; ti[s] = ti[s-1]; ti[s-1] = b;
            }
        }
    }
}

__global__ void __launch_bounds__(NTH, 2)
attn_kernel(const float* __restrict__ qg_, const float* __restrict__ kg_,
            const float* __restrict__ vg_, float* __restrict__ og_) {
    extern __shared__ float smem[];
    float* ssc = smem;                       // [128][132] score tile + scratch
    float* qsm = smem + SSC_FL;              // [2][CHUNK][128] plain q
    float* ksm = qsm + 2 * QBUF_FL;          // [2][CHUNK][128]

    // grid (128, 8): x = bh (fast), y = qt-rank. Heavy -> light bid order.
    const int bh  = blockIdx.x;
    const int qt  = (gridDim.y - 1) - blockIdx.y;
    const int tid = threadIdx.x;

    // warp tile 32 rows x 64 cols: fewer distinct b-lanes per warp
    // -> smem crossbar 10 -> 6 cyc/warp/d. Element->(d-order) unchanged.
    const int w   = tid >> 5;
    const int l   = tid & 31;
    const int tr  = (w >> 1) * 4 + (l >> 3);
    const int tc  = (w & 1) * 8 + (l & 7);

    const float* qg = qg_ + ((size_t)bh * SEQ + (size_t)qt * QT) * DKH;
    const float* kg = kg_ + (size_t)bh * SEQ * DKH;
    const float* vg = vg_ + (size_t)bh * SEQ * DKH;
    float*       og = og_ + ((size_t)bh * SEQ + (size_t)qt * QT) * DKH;

    const int q    = tid & 127;
    const int half = tid >> 7;
    const int row_l = tid & 127;
    const int dq_l  = (tid >> 7) * 4;        // which float4 of the 8-d chunk

    const float tscale = 0.12751743f;        // (1/sqrt(128)) * log2(e)

    const ull kMG   = pk2(12582912.0f, 12582912.0f);
    const ull kNMG  = pk2(-12582912.0f, -12582912.0f);
    const ull kNEG1 = pk2(-1.0f, -1.0f);
    const ull kC5   = pk2(1.3333558e-3f, 1.3333558e-3f);
    const ull kC4   = pk2(9.6181291e-3f, 9.6181291e-3f);
    const ull kC3   = pk2(5.5504109e-2f, 5.5504109e-2f);
    const ull kC2   = pk2(2.4022651e-1f, 2.4022651e-1f);
    const ull kC1   = pk2(6.9314718e-1f, 6.9314718e-1f);
    const ull kC0   = pk2(1.0f, 1.0f);

    float m = -1.0e30f, Z = 0.0f;
    ull negm2 = pk2(1.0e30f, 1.0e30f);
    float tv[5]; int tix[5];
    #pragma unroll
    for (int i = 0; i < 5; i++) { tv[i] = SENT; tix[i] = 0; }
    float sf[KIDX];
    #pragma unroll
    for (int i = 0; i < KIDX; i++) sf[i] = TMASK;
    const bool rec = (qt == 0) && (half == 0) && (q < KIDX);

    for (int kt = 0; kt <= qt; kt++) {
        const float* kgt = kg + (size_t)kt * QT * DKH;

        ull acc2[8][4];
        #pragma unroll
        for (int i = 0; i < 8; i++)
            #pragma unroll
            for (int j = 0; j < 4; j++) acc2[i][j] = 0ULL;

        float4 qv, kv;
        qv = *(const float4*)(qg  + (size_t)row_l * DKH + dq_l);
        kv = *(const float4*)(kgt + (size_t)row_l * DKH + dq_l);
        {   float* qd = qsm; float* kd = ksm;
            qd[(dq_l+0)*128 + row_l] = qv.x;
            qd[(dq_l+1)*128 + row_l] = qv.y;
            qd[(dq_l+2)*128 + row_l] = qv.z;
            qd[(dq_l+3)*128 + row_l] = qv.w;
            kd[(dq_l+0)*128 + row_l] = kv.x;
            kd[(dq_l+1)*128 + row_l] = kv.y;
            kd[(dq_l+2)*128 + row_l] = kv.z;
            kd[(dq_l+3)*128 + row_l] = kv.w;
        }
        __syncthreads();

        for (int c = 0; c < NCHUNK; c++) {
            if (c + 1 < NCHUNK) {
                int dbase = (c + 1) * CHUNK;
                qv = *(const float4*)(qg  + (size_t)row_l * DKH + dbase + dq_l);
                kv = *(const float4*)(kgt + (size_t)row_l * DKH + dbase + dq_l);
            }
            const float* qb = qsm + (c & 1) * QBUF_FL;
            const float* kb = ksm + (c & 1) * KBUF_FL;
            #pragma unroll
            for (int d = 0; d < CHUNK; d++) {
                U4 a0, a1, b0, b1;
                a0.f = *(const float4*)(qb + d * 128 + tr * 8);
                a1.f = *(const float4*)(qb + d * 128 + tr * 8 + 4);
                b0.f = *(const float4*)(kb + d * 128 + tc * 8);
                b1.f = *(const float4*)(kb + d * 128 + tc * 8 + 4);
                float av[8] = {a0.f.x, a0.f.y, a0.f.z, a0.f.w,
                               a1.f.x, a1.f.y, a1.f.z, a1.f.w};
                #pragma unroll
                for (int i = 0; i < 8; i++) {
                    ull ad = pk2(av[i], av[i]);
                    acc2[i][0] = fma2v(ad, b0.u[0], acc2[i][0]);
                    acc2[i][1] = fma2v(ad, b0.u[1], acc2[i][1]);
                    acc2[i][2] = fma2v(ad, b1.u[0], acc2[i][2]);
                    acc2[i][3] = fma2v(ad, b1.u[1], acc2[i][3]);
                }
            }
            if (c + 1 < NCHUNK) {
                float* qd = qsm + ((c + 1) & 1) * QBUF_FL;
                float* kd = ksm + ((c + 1) & 1) * KBUF_FL;
                qd[(dq_l+0)*128 + row_l] = qv.x;
                qd[(dq_l+1)*128 + row_l] = qv.y;
                qd[(dq_l+2)*128 + row_l] = qv.z;
                qd[(dq_l+3)*128 + row_l] = qv.w;
                kd[(dq_l+0)*128 + row_l] = kv.x;
                kd[(dq_l+1)*128 + row_l] = kv.y;
                kd[(dq_l+2)*128 + row_l] = kv.z;
                kd[(dq_l+3)*128 + row_l] = kv.w;
                __syncthreads();
            }
        }

        // write score tile in t-space, causal mask on diag tile
        const bool diag = (kt == qt);
        #pragma unroll
        for (int i = 0; i < 8; i++) {
            int qrow = tr * 8 + i;
            float s[8];
            #pragma unroll
            for (int jp = 0; jp < 4; jp++) {
                float lo, hi;
                asm("mov.b64 {%0,%1}, %2;" : "=f"(lo), "=f"(hi) : "l"(acc2[i][jp]));
                s[2*jp]   = lo * tscale;
                s[2*jp+1] = hi * tscale;
            }
            #pragma unroll
            for (int j = 0; j < 8; j++) {
                int kcol = tc * 8 + j;
                if (diag && kcol > qrow) s[j] = TMASK;
            }
            float4* dst = (float4*)(ssc + qrow * SPITCH + tc * 8);
            dst[0] = make_float4(s[0], s[1], s[2], s[3]);
            dst[1] = make_float4(s[4], s[5], s[6], s[7]);
        }
        __syncthreads();

        // scan: 2 threads/row, 64 elems each (fixed 16-group unrolled body)
        const float* srowf = ssc + q * SPITCH + half * 64;
        const int kb0 = kt * QT + half * 64;
        #pragma unroll 4
        for (int g = 0; g < 16; g++) {
            U4 t4; t4.f = *(const float4*)(srowf + g * 4);
            if (rec && kt == 0) {
                if (g == 0) { sf[0]=t4.f.x; sf[1]=t4.f.y; sf[2]=t4.f.z; sf[3]=t4.f.w; }
                else if (g == 1) { sf[4]=t4.f.x; }
            }
            float gm = fmaxf(fmaxf(t4.f.x, t4.f.y), fmaxf(t4.f.z, t4.f.w));
            if (gm > m) {
                float sc = fexp2(m - gm);
                Z *= sc; m = gm;
                negm2 = pk2(-m, -m);
            }
            float ex, ey, ez, ew;
            PEXP2(t4.u[0], negm2, ex, ey);
            PEXP2(t4.u[1], negm2, ez, ew);
            Z += ex; Z += ey; Z += ez; Z += ew;   // original scalar order
            if (gm > tv[4]) {
                int kb = kb0 + g * 4;
                ins5(t4.f.x, kb + 0, tv, tix);
                ins5(t4.f.y, kb + 1, tv, tix);
                ins5(t4.f.z, kb + 2, tv, tix);
                ins5(t4.f.w, kb + 3, tv, tix);
            }
        }
        // no sync needed: next tile's staging buffers are disjoint from ssc,
        // and ssc is rewritten only after the chunk-loop barriers
    }

    // inline Sum(v) for qt==0 (only rows 1..4 consume it); qt0 CTAs are in the
    // light tail wave so this extra work is fully absorbed
    if (qt == 0) {
        int d = tid & 127, part = tid >> 7;
        const float* vp = vg + (size_t)part * 512 * DKH + d;
        float s0 = 0.f, s1 = 0.f, s2 = 0.f, s3 = 0.f;
        #pragma unroll 4
        for (int r = 0; r < 512; r += 4) {
            s0 += vp[(size_t)(r+0) * DKH];
            s1 += vp[(size_t)(r+1) * DKH];
            s2 += vp[(size_t)(r+2) * DKH];
            s3 += vp[(size_t)(r+3) * DKH];
        }
        ssc[VSUM_OFF + part * 128 + d] = (s0 + s1) + (s2 + s3);
    }

    __syncthreads();

    // publish half=1 state
    if (half) {
        float* pp = ssc + q * 24;
        pp[0] = m; pp[1] = Z;
        #pragma unroll
        for (int s = 0; s < 5; s++) { pp[2+s] = tv[s]; ((int*)pp)[7+s] = tix[s]; }
    }
    __syncthreads();

    // merge + finalize weights (half=0 threads)
    if (!half) {
        const float* pp = ssc + q * 24;
        float m1 = pp[0], Z1 = pp[1];
        float mm = fmaxf(m, m1);
        float Zm = Z * fexp2(fmaxf(m - mm, -126.0f)) + Z1 * fexp2(fmaxf(m1 - mm, -126.0f));
        #pragma unroll
        for (int s = 0; s < 5; s++) ins5(pp[2+s], ((const int*)pp)[7+s], tv, tix);

        int r = qt * QT + q;
        float wv[5]; int wi[5]; float cu = 0.0f;
        #pragma unroll
        for (int i = 0; i < 5; i++) { wv[i] = 0.0f; wi[i] = 0; }

        if (r >= KIDX) {
            float e[5], D = 0.0f;
            float invZ = 1.0f / Zm;
            #pragma unroll
            for (int i = 0; i < 5; i++) {
                float p = fexp2(tv[i] - mm) * invZ;   // first-softmax prob
                e[i] = __expf(p);
                D += e[i];
            }
            float inv = 1.0f / D;
            #pragma unroll
            for (int i = 0; i < 5; i++) { wv[i] = e[i] * inv; wi[i] = tix[i]; }
        } else if (r >= 1) {
            float D = (float)(SEQ - 1 - r);
            float e[KIDX];
            float invZ = 1.0f / Zm;
            #pragma unroll
            for (int j = 0; j < KIDX; j++) {
                e[j] = 0.0f;
                if (j <= r) {
                    float p = fexp2(sf[j] - mm) * invZ;
                    e[j] = expm1f(p);                 // e^p - 1
                    D += e[j] + 1.0f;
                }
            }
            float inv = 1.0f / D;
            cu = inv;
            #pragma unroll
            for (int j = 0; j < KIDX; j++) {
                if (j <= r) { wv[j] = e[j] * inv; wi[j] = j; }
            }
        }
        float* fs = ssc + 4096 + q * 12;
        fs[0] = cu;
        #pragma unroll
        for (int i = 0; i < 5; i++) { fs[1+i] = wv[i]; ((int*)fs)[6+i] = wi[i]; }
    }
    __syncthreads();

    // gather epilogue: 2 threads/row, 64 dims each
    {
        const float* fs = ssc + 4096 + q * 12;
        float cu = fs[0];
        float w0 = fs[1], w1 = fs[2], w2 = fs[3], w3 = fs[4], w4 = fs[5];
        const int* ip = (const int*)fs;
        const float4* v0 = (const float4*)(vg + (size_t)ip[6]  * DKH + half * 64);
        const float4* v1 = (const float4*)(vg + (size_t)ip[7]  * DKH + half * 64);
        const float4* v2 = (const float4*)(vg + (size_t)ip[8]  * DKH + half * 64);
        const float4* v3 = (const float4*)(vg + (size_t)ip[9]  * DKH + half * 64);
        const float4* v4 = (const float4*)(vg + (size_t)ip[10] * DKH + half * 64);
        const float4* p0 = (const float4*)(ssc + VSUM_OFF + half * 64);
        const float4* p1 = (const float4*)(ssc + VSUM_OFF + 128 + half * 64);
        float4* op = (float4*)(og + (size_t)q * DKH + half * 64);
        const bool hasvs = (qt == 0);
        #pragma unroll
        for (int d = 0; d < 16; d++) {
            float4 o4 = make_float4(0.f, 0.f, 0.f, 0.f);
            if (hasvs) {
                float4 a0 = p0[d], a1 = p1[d];
                o4.x = cu * (a0.x + a1.x); o4.y = cu * (a0.y + a1.y);
                o4.z = cu * (a0.z + a1.z); o4.w = cu * (a0.w + a1.w);
            }
            float4 b;
            b = v0[d]; o4.x=fmaf(w0,b.x,o4.x); o4.y=fmaf(w0,b.y,o4.y); o4.z=fmaf(w0,b.z,o4.z); o4.w=fmaf(w0,b.w,o4.w);
            b = v1[d]; o4.x=fmaf(w1,b.x,o4.x); o4.y=fmaf(w1,b.y,o4.y); o4.z=fmaf(w1,b.z,o4.z); o4.w=fmaf(w1,b.w,o4.w);
            b = v2[d]; o4.x=fmaf(w2,b.x,o4.x); o4.y=fmaf(w2,b.y,o4.y); o4.z=fmaf(w2,b.z,o4.z); o4.w=fmaf(w2,b.w,o4.w);
            b = v3[d]; o4.x=fmaf(w3,b.x,o4.x); o4.y=fmaf(w3,b.y,o4.y); o4.z=fmaf(w3,b.z,o4.z); o4.w=fmaf(w3,b.w,o4.w);
            b = v4[d]; o4.x=fmaf(w4,b.x,o4.x); o4.y=fmaf(w4,b.y,o4.y); o4.z=fmaf(w4,b.z,o4.z); o4.w=fmaf(w4,b.w,o4.w);
            op[d] = o4;
        }
    }
}

extern "C" void kernel_launch(void* const* d_in, const int* in_sizes, int n_in,
                              void* d_out, int out_size) {
    const float* q = (const float*)d_in[0];
    const float* k = (const float*)d_in[1];
    const float* v = (const float*)d_in[2];
    float* o = (float*)d_out;
    cudaFuncSetAttribute(attn_kernel, cudaFuncAttributeMaxDynamicSharedMemorySize, SMEMSZ);
    attn_kernel<<<dim3(128, 8), NTH, SMEMSZ>>>(q, k, v, o);
}

// round 10
// speedup vs baseline: 1.0170x; 1.0170x over previous
#include <cuda_runtime.h>

#define SEQ 1024
#define DKH 128
#define KIDX 5
#define QT 128
#define NTH 256
#define CHUNK 16
#define NCHUNK 8
#define SPITCH 132
#define TMASK (-80.0f)
#define SENT (-1.0e31f)
// ssc [128][132] = 16896 floats. Staging double-buffers ALIAS its front:
//   q 2*16*128 = 4096 fl at [0,4096), k 2*16*128 = 4096 fl at [4096,8192).
// Safe: barriers order staging-read -> score-write -> scan-read -> next staging.
#define SSC_FL   (QT * SPITCH)
#define QBUF_FL  (CHUNK * 128)
#define KBUF_FL  (CHUNK * 128)
#define SMEMSZ   (SSC_FL * 4)
#define VSUM_OFF 6144

typedef unsigned long long ull;

__device__ __forceinline__ ull pk2(float a, float b) {
    ull r;
    asm("mov.b64 %0, {%1, %2};" : "=l"(r) : "f"(a), "f"(b));
    return r;
}
__device__ __forceinline__ ull fma2v(ull a, ull b, ull c) {
    ull d;
    asm("fma.rn.f32x2 %0, %1, %2, %3;" : "=l"(d) : "l"(a), "l"(b), "l"(c));
    return d;
}
__device__ __forceinline__ ull add2v(ull a, ull b) {
    ull d;
    asm("add.rn.f32x2 %0, %1, %2;" : "=l"(d) : "l"(a), "l"(b));
    return d;
}

union U4 { float4 f; ull u[2]; };

// scalar 2^x (x in [-130, 0])
__device__ __forceinline__ float fexp2(float x) {
    float fz = x + 12582912.0f;
    float r  = x - (fz - 12582912.0f);
    float p  = 1.3333558e-3f;
    p = fmaf(p, r, 9.6181291e-3f);
    p = fmaf(p, r, 5.5504109e-2f);
    p = fmaf(p, r, 2.4022651e-1f);
    p = fmaf(p, r, 6.9314718e-1f);
    p = fmaf(p, r, 1.0f);
    return __int_as_float(__float_as_int(p) + (__float_as_int(fz) << 23));
}

// packed pair 2^x -> two scalars (bit-identical per lane to fexp2)
#define PEXP2(t2, negm2, r0, r1) do {                                   \
    ull x2_  = add2v((t2), (negm2));                                    \
    ull fz2_ = add2v(x2_, kMG);                                         \
    ull e2_  = add2v(fz2_, kNMG);                                       \
    ull r2_  = fma2v(e2_, kNEG1, x2_);                                  \
    ull p2_  = fma2v(kC5, r2_, kC4);                                    \
    p2_ = fma2v(p2_, r2_, kC3);                                         \
    p2_ = fma2v(p2_, r2_, kC2);                                         \
    p2_ = fma2v(p2_, r2_, kC1);                                         \
    p2_ = fma2v(p2_, r2_, kC0);                                         \
    unsigned fzl_, fzh_, pl_, ph_;                                      \
    asm("mov.b64 {%0,%1}, %2;" : "=r"(fzl_), "=r"(fzh_) : "l"(fz2_));   \
    asm("mov.b64 {%0,%1}, %2;" : "=r"(pl_), "=r"(ph_) : "l"(p2_));      \
    (r0) = __int_as_float((int)(pl_ + (fzl_ << 23)));                   \
    (r1) = __int_as_float((int)(ph_ + (fzh_ << 23)));                   \
} while (0)

__device__ __forceinline__ void ins5(float t, int idx, float tv[5], int ti[5]) {
    if (t > tv[4]) {
        tv[4] = t; ti[4] = idx;
        #pragma unroll
        for (int s = 4; s > 0; s--) {
            if (tv[s] > tv[s-1]) {
                float a = tv[s]; tv[s] = tv[s-1]; tv[s-1] = a;
                int   b = ti[s]; ti[s] = ti[s-1]; ti[s-1] = b;
            }
        }
    }
}

__global__ void __launch_bounds__(NTH, 2)
attn_kernel(const float* __restrict__ qg_, const float* __restrict__ kg_,
            const float* __restrict__ vg_, float* __restrict__ og_) {
    extern __shared__ float smem[];
    float* ssc = smem;                       // [128][132] score tile (phase 2)
    float* qsm = smem;                       // alias: [2][16][128] q (phase 1)
    float* ksm = smem + 2 * QBUF_FL;         // alias: [2][16][128] k (phase 1)

    // grid (128, 8): x = bh (fast), y = qt-rank. Heavy -> light bid order.
    const int bh  = blockIdx.x;
    const int qt  = (gridDim.y - 1) - blockIdx.y;
    const int tid = threadIdx.x;
    const int tr  = tid >> 4;
    const int tc  = tid & 15;

    const float* qg = qg_ + ((size_t)bh * SEQ + (size_t)qt * QT) * DKH;
    const float* kg = kg_ + (size_t)bh * SEQ * DKH;
    const float* vg = vg_ + (size_t)bh * SEQ * DKH;
    float*       og = og_ + ((size_t)bh * SEQ + (size_t)qt * QT) * DKH;

    const int q    = tid & 127;
    const int half = tid >> 7;
    const int row_l = tid & 127;
    const int dq_l  = (tid >> 7) * 8;        // 8 d-layers per thread per chunk

    const float tscale = 0.12751743f;        // (1/sqrt(128)) * log2(e)

    const ull kMG   = pk2(12582912.0f, 12582912.0f);
    const ull kNMG  = pk2(-12582912.0f, -12582912.0f);
    const ull kNEG1 = pk2(-1.0f, -1.0f);
    const ull kC5   = pk2(1.3333558e-3f, 1.3333558e-3f);
    const ull kC4   = pk2(9.6181291e-3f, 9.6181291e-3f);
    const ull kC3   = pk2(5.5504109e-2f, 5.5504109e-2f);
    const ull kC2   = pk2(2.4022651e-1f, 2.4022651e-1f);
    const ull kC1   = pk2(6.9314718e-1f, 6.9314718e-1f);
    const ull kC0   = pk2(1.0f, 1.0f);

    float m = -1.0e30f, Z = 0.0f;
    ull negm2 = pk2(1.0e30f, 1.0e30f);
    float tv[5]; int tix[5];
    #pragma unroll
    for (int i = 0; i < 5; i++) { tv[i] = SENT; tix[i] = 0; }
    float sf[KIDX];
    #pragma unroll
    for (int i = 0; i < KIDX; i++) sf[i] = TMASK;
    const bool rec = (qt == 0) && (half == 0) && (q < KIDX);

    for (int kt = 0; kt <= qt; kt++) {
        const float* kgt = kg + (size_t)kt * QT * DKH;

        ull acc2[8][4];
        #pragma unroll
        for (int i = 0; i < 8; i++)
            #pragma unroll
            for (int j = 0; j < 4; j++) acc2[i][j] = 0ULL;

        float4 qv0, qv1, kv0, kv1;
        qv0 = *(const float4*)(qg  + (size_t)row_l * DKH + dq_l);
        qv1 = *(const float4*)(qg  + (size_t)row_l * DKH + dq_l + 4);
        kv0 = *(const float4*)(kgt + (size_t)row_l * DKH + dq_l);
        kv1 = *(const float4*)(kgt + (size_t)row_l * DKH + dq_l + 4);
        {   float* qd = qsm; float* kd = ksm;
            qd[(dq_l+0)*128 + row_l] = qv0.x;
            qd[(dq_l+1)*128 + row_l] = qv0.y;
            qd[(dq_l+2)*128 + row_l] = qv0.z;
            qd[(dq_l+3)*128 + row_l] = qv0.w;
            qd[(dq_l+4)*128 + row_l] = qv1.x;
            qd[(dq_l+5)*128 + row_l] = qv1.y;
            qd[(dq_l+6)*128 + row_l] = qv1.z;
            qd[(dq_l+7)*128 + row_l] = qv1.w;
            kd[(dq_l+0)*128 + row_l] = kv0.x;
            kd[(dq_l+1)*128 + row_l] = kv0.y;
            kd[(dq_l+2)*128 + row_l] = kv0.z;
            kd[(dq_l+3)*128 + row_l] = kv0.w;
            kd[(dq_l+4)*128 + row_l] = kv1.x;
            kd[(dq_l+5)*128 + row_l] = kv1.y;
            kd[(dq_l+6)*128 + row_l] = kv1.z;
            kd[(dq_l+7)*128 + row_l] = kv1.w;
        }
        __syncthreads();

        for (int c = 0; c < NCHUNK; c++) {
            if (c + 1 < NCHUNK) {
                int dbase = (c + 1) * CHUNK;
                qv0 = *(const float4*)(qg  + (size_t)row_l * DKH + dbase + dq_l);
                qv1 = *(const float4*)(qg  + (size_t)row_l * DKH + dbase + dq_l + 4);
                kv0 = *(const float4*)(kgt + (size_t)row_l * DKH + dbase + dq_l);
                kv1 = *(const float4*)(kgt + (size_t)row_l * DKH + dbase + dq_l + 4);
            }
            const float* qb = qsm + (c & 1) * QBUF_FL;
            const float* kb = ksm + (c & 1) * KBUF_FL;
            #pragma unroll
            for (int d = 0; d < CHUNK; d++) {
                U4 a0, a1, b0, b1;
                a0.f = *(const float4*)(qb + d * 128 + tr * 8);
                a1.f = *(const float4*)(qb + d * 128 + tr * 8 + 4);
                b0.f = *(const float4*)(kb + d * 128 + tc * 8);
                b1.f = *(const float4*)(kb + d * 128 + tc * 8 + 4);
                float av[8] = {a0.f.x, a0.f.y, a0.f.z, a0.f.w,
                               a1.f.x, a1.f.y, a1.f.z, a1.f.w};
                #pragma unroll
                for (int i = 0; i < 8; i++) {
                    ull ad = pk2(av[i], av[i]);
                    acc2[i][0] = fma2v(ad, b0.u[0], acc2[i][0]);
                    acc2[i][1] = fma2v(ad, b0.u[1], acc2[i][1]);
                    acc2[i][2] = fma2v(ad, b1.u[0], acc2[i][2]);
                    acc2[i][3] = fma2v(ad, b1.u[1], acc2[i][3]);
                }
            }
            if (c + 1 < NCHUNK) {
                float* qd = qsm + ((c + 1) & 1) * QBUF_FL;
                float* kd = ksm + ((c + 1) & 1) * KBUF_FL;
                qd[(dq_l+0)*128 + row_l] = qv0.x;
                qd[(dq_l+1)*128 + row_l] = qv0.y;
                qd[(dq_l+2)*128 + row_l] = qv0.z;
                qd[(dq_l+3)*128 + row_l] = qv0.w;
                qd[(dq_l+4)*128 + row_l] = qv1.x;
                qd[(dq_l+5)*128 + row_l] = qv1.y;
                qd[(dq_l+6)*128 + row_l] = qv1.z;
                qd[(dq_l+7)*128 + row_l] = qv1.w;
                kd[(dq_l+0)*128 + row_l] = kv0.x;
                kd[(dq_l+1)*128 + row_l] = kv0.y;
                kd[(dq_l+2)*128 + row_l] = kv0.z;
                kd[(dq_l+3)*128 + row_l] = kv0.w;
                kd[(dq_l+4)*128 + row_l] = kv1.x;
                kd[(dq_l+5)*128 + row_l] = kv1.y;
                kd[(dq_l+6)*128 + row_l] = kv1.z;
                kd[(dq_l+7)*128 + row_l] = kv1.w;
            }
            __syncthreads();   // also fences last chunk's buffer reads before ssc writes
        }

        // write score tile in t-space, causal mask on diag tile
        const bool diag = (kt == qt);
        #pragma unroll
        for (int i = 0; i < 8; i++) {
            int qrow = tr * 8 + i;
            float s[8];
            #pragma unroll
            for (int jp = 0; jp < 4; jp++) {
                float lo, hi;
                asm("mov.b64 {%0,%1}, %2;" : "=f"(lo), "=f"(hi) : "l"(acc2[i][jp]));
                s[2*jp]   = lo * tscale;
                s[2*jp+1] = hi * tscale;
            }
            #pragma unroll
            for (int j = 0; j < 8; j++) {
                int kcol = tc * 8 + j;
                if (diag && kcol > qrow) s[j] = TMASK;
            }
            float4* dst = (float4*)(ssc + qrow * SPITCH + tc * 8);
            dst[0] = make_float4(s[0], s[1], s[2], s[3]);
            dst[1] = make_float4(s[4], s[5], s[6], s[7]);
        }
        __syncthreads();

        // scan: 2 threads/row, 64 elems each (fixed 16-group unrolled body)
        const float* srowf = ssc + q * SPITCH + half * 64;
        const int kb0 = kt * QT + half * 64;
        #pragma unroll 4
        for (int g = 0; g < 16; g++) {
            U4 t4; t4.f = *(const float4*)(srowf + g * 4);
            if (rec && kt == 0) {
                if (g == 0) { sf[0]=t4.f.x; sf[1]=t4.f.y; sf[2]=t4.f.z; sf[3]=t4.f.w; }
                else if (g == 1) { sf[4]=t4.f.x; }
            }
            float gm = fmaxf(fmaxf(t4.f.x, t4.f.y), fmaxf(t4.f.z, t4.f.w));
            if (gm > m) {
                float sc = fexp2(m - gm);
                Z *= sc; m = gm;
                negm2 = pk2(-m, -m);
            }
            float ex, ey, ez, ew;
            PEXP2(t4.u[0], negm2, ex, ey);
            PEXP2(t4.u[1], negm2, ez, ew);
            Z += ex; Z += ey; Z += ez; Z += ew;   // original scalar order
            if (gm > tv[4]) {
                int kb = kb0 + g * 4;
                ins5(t4.f.x, kb + 0, tv, tix);
                ins5(t4.f.y, kb + 1, tv, tix);
                ins5(t4.f.z, kb + 2, tv, tix);
                ins5(t4.f.w, kb + 3, tv, tix);
            }
        }
        __syncthreads();   // scan reads done before next tile's aliased staging
    }

    // inline Sum(v) for qt==0 (only rows 1..4 consume it); qt0 CTAs are in the
    // light tail wave so this extra work is fully absorbed
    if (qt == 0) {
        int d = tid & 127, part = tid >> 7;
        const float* vp = vg + (size_t)part * 512 * DKH + d;
        float s0 = 0.f, s1 = 0.f, s2 = 0.f, s3 = 0.f;
        #pragma unroll 4
        for (int r = 0; r < 512; r += 4) {
            s0 += vp[(size_t)(r+0) * DKH];
            s1 += vp[(size_t)(r+1) * DKH];
            s2 += vp[(size_t)(r+2) * DKH];
            s3 += vp[(size_t)(r+3) * DKH];
        }
        ssc[VSUM_OFF + part * 128 + d] = (s0 + s1) + (s2 + s3);
    }

    __syncthreads();

    // publish half=1 state
    if (half) {
        float* pp = ssc + q * 24;
        pp[0] = m; pp[1] = Z;
        #pragma unroll
        for (int s = 0; s < 5; s++) { pp[2+s] = tv[s]; ((int*)pp)[7+s] = tix[s]; }
    }
    __syncthreads();

    // merge + finalize weights (half=0 threads)
    if (!half) {
        const float* pp = ssc + q * 24;
        float m1 = pp[0], Z1 = pp[1];
        float mm = fmaxf(m, m1);
        float Zm = Z * fexp2(fmaxf(m - mm, -126.0f)) + Z1 * fexp2(fmaxf(m1 - mm, -126.0f));
        #pragma unroll
        for (int s = 0; s < 5; s++) ins5(pp[2+s], ((const int*)pp)[7+s], tv, tix);

        int r = qt * QT + q;
        float wv[5]; int wi[5]; float cu = 0.0f;
        #pragma unroll
        for (int i = 0; i < 5; i++) { wv[i] = 0.0f; wi[i] = 0; }

        if (r >= KIDX) {
            float e[5], D = 0.0f;
            float invZ = 1.0f / Zm;
            #pragma unroll
            for (int i = 0; i < 5; i++) {
                float p = fexp2(tv[i] - mm) * invZ;   // first-softmax prob
                e[i] = __expf(p);
                D += e[i];
            }
            float inv = 1.0f / D;
            #pragma unroll
            for (int i = 0; i < 5; i++) { wv[i] = e[i] * inv; wi[i] = tix[i]; }
        } else if (r >= 1) {
            float D = (float)(SEQ - 1 - r);
            float e[KIDX];
            float invZ = 1.0f / Zm;
            #pragma unroll
            for (int j = 0; j < KIDX; j++) {
                e[j] = 0.0f;
                if (j <= r) {
                    float p = fexp2(sf[j] - mm) * invZ;
                    e[j] = expm1f(p);                 // e^p - 1
                    D += e[j] + 1.0f;
                }
            }
            float inv = 1.0f / D;
            cu = inv;
            #pragma unroll
            for (int j = 0; j < KIDX; j++) {
                if (j <= r) { wv[j] = e[j] * inv; wi[j] = j; }
            }
        }
        float* fs = ssc + 4096 + q * 12;
        fs[0] = cu;
        #pragma unroll
        for (int i = 0; i < 5; i++) { fs[1+i] = wv[i]; ((int*)fs)[6+i] = wi[i]; }
    }
    __syncthreads();

    // gather epilogue: 2 threads/row, 64 dims each
    {
        const float* fs = ssc + 4096 + q * 12;
        float cu = fs[0];
        float w0 = fs[1], w1 = fs[2], w2 = fs[3], w3 = fs[4], w4 = fs[5];
        const int* ip = (const int*)fs;
        const float4* v0 = (const float4*)(vg + (size_t)ip[6]  * DKH + half * 64);
        const float4* v1 = (const float4*)(vg + (size_t)ip[7]  * DKH + half * 64);
        const float4* v2 = (const float4*)(vg + (size_t)ip[8]  * DKH + half * 64);
        const float4* v3 = (const float4*)(vg + (size_t)ip[9]  * DKH + half * 64);
        const float4* v4 = (const float4*)(vg + (size_t)ip[10] * DKH + half * 64);
        const float4* p0 = (const float4*)(ssc + VSUM_OFF + half * 64);
        const float4* p1 = (const float4*)(ssc + VSUM_OFF + 128 + half * 64);
        float4* op = (float4*)(og + (size_t)q * DKH + half * 64);
        const bool hasvs = (qt == 0);
        #pragma unroll
        for (int d = 0; d < 16; d++) {
            float4 o4 = make_float4(0.f, 0.f, 0.f, 0.f);
            if (hasvs) {
                float4 a0 = p0[d], a1 = p1[d];
                o4.x = cu * (a0.x + a1.x); o4.y = cu * (a0.y + a1.y);
                o4.z = cu * (a0.z + a1.z); o4.w = cu * (a0.w + a1.w);
            }
            float4 b;
            b = v0[d]; o4.x=fmaf(w0,b.x,o4.x); o4.y=fmaf(w0,b.y,o4.y); o4.z=fmaf(w0,b.z,o4.z); o4.w=fmaf(w0,b.w,o4.w);
            b = v1[d]; o4.x=fmaf(w1,b.x,o4.x); o4.y=fmaf(w1,b.y,o4.y); o4.z=fmaf(w1,b.z,o4.z); o4.w=fmaf(w1,b.w,o4.w);
            b = v2[d]; o4.x=fmaf(w2,b.x,o4.x); o4.y=fmaf(w2,b.y,o4.y); o4.z=fmaf(w2,b.z,o4.z); o4.w=fmaf(w2,b.w,o4.w);
            b = v3[d]; o4.x=fmaf(w3,b.x,o4.x); o4.y=fmaf(w3,b.y,o4.y); o4.z=fmaf(w3,b.z,o4.z); o4.w=fmaf(w3,b.w,o4.w);
            b = v4[d]; o4.x=fmaf(w4,b.x,o4.x); o4.y=fmaf(w4,b.y,o4.y); o4.z=fmaf(w4,b.z,o4.z); o4.w=fmaf(w4,b.w,o4.w);
            op[d] = o4;
        }
    }
}

extern "C" void kernel_launch(void* const* d_in, const int* in_sizes, int n_in,
                              void* d_out, int out_size) {
    const float* q = (const float*)d_in[0];
    const float* k = (const float*)d_in[1];
    const float* v = (const float*)d_in[2];
    float* o = (float*)d_out;
    cudaFuncSetAttribute(attn_kernel, cudaFuncAttributeMaxDynamicSharedMemorySize, SMEMSZ);
    attn_kernel<<<dim3(128, 8), NTH, SMEMSZ>>>(q, k, v, o);
}

// round 11
// speedup vs baseline: 1.0354x; 1.0181x over previous
#include <cuda_runtime.h>

#define SEQ 1024
#define DKH 128
#define KIDX 5
#define QT 128
#define NTH 256
#define CHUNK 8
#define NCHUNK 16
#define SPITCH 132
#define TMASK (-80.0f)
#define SENT (-1.0e31f)
// smem: ssc 128*132 = 16896 | q 2*8*128 = 2048 | k 2*8*128 = 2048
#define SSC_FL   (QT * SPITCH)
#define QBUF_FL  (CHUNK * 128)
#define KBUF_FL  (CHUNK * 128)
#define SMEM_FLOATS (SSC_FL + 2 * QBUF_FL + 2 * KBUF_FL)
#define SMEMSZ (SMEM_FLOATS * 4)
#define VSUM_OFF 6144

typedef unsigned long long ull;

__device__ __forceinline__ ull pk2(float a, float b) {
    ull r;
    asm("mov.b64 %0, {%1, %2};" : "=l"(r) : "f"(a), "f"(b));
    return r;
}
__device__ __forceinline__ ull fma2v(ull a, ull b, ull c) {
    ull d;
    asm("fma.rn.f32x2 %0, %1, %2, %3;" : "=l"(d) : "l"(a), "l"(b), "l"(c));
    return d;
}
__device__ __forceinline__ ull add2v(ull a, ull b) {
    ull d;
    asm("add.rn.f32x2 %0, %1, %2;" : "=l"(d) : "l"(a), "l"(b));
    return d;
}
__device__ __forceinline__ ull mul2v(ull a, ull b) {
    ull d;
    asm("mul.rn.f32x2 %0, %1, %2;" : "=l"(d) : "l"(a), "l"(b));
    return d;
}

union U4 { float4 f; ull u[2]; };

// scalar 2^x (x in [-130, 0])
__device__ __forceinline__ float fexp2(float x) {
    float fz = x + 12582912.0f;
    float r  = x - (fz - 12582912.0f);
    float p  = 1.3333558e-3f;
    p = fmaf(p, r, 9.6181291e-3f);
    p = fmaf(p, r, 5.5504109e-2f);
    p = fmaf(p, r, 2.4022651e-1f);
    p = fmaf(p, r, 6.9314718e-1f);
    p = fmaf(p, r, 1.0f);
    return __int_as_float(__float_as_int(p) + (__float_as_int(fz) << 23));
}

// packed pair 2^x -> ONE packed result (each lane bit-identical to fexp2)
#define PEXP2P(t2, negm2, out2) do {                                    \
    ull x2_  = add2v((t2), (negm2));                                    \
    ull fz2_ = add2v(x2_, kMG);                                         \
    ull e2_  = add2v(fz2_, kNMG);                                       \
    ull r2_  = fma2v(e2_, kNEG1, x2_);                                  \
    ull p2_  = fma2v(kC5, r2_, kC4);                                    \
    p2_ = fma2v(p2_, r2_, kC3);                                         \
    p2_ = fma2v(p2_, r2_, kC2);                                         \
    p2_ = fma2v(p2_, r2_, kC1);                                         \
    p2_ = fma2v(p2_, r2_, kC0);                                         \
    unsigned fzl_, fzh_, pl_, ph_;                                      \
    asm("mov.b64 {%0,%1}, %2;" : "=r"(fzl_), "=r"(fzh_) : "l"(fz2_));   \
    asm("mov.b64 {%0,%1}, %2;" : "=r"(pl_), "=r"(ph_) : "l"(p2_));      \
    unsigned rl_ = pl_ + (fzl_ << 23);                                  \
    unsigned rh_ = ph_ + (fzh_ << 23);                                  \
    asm("mov.b64 %0, {%1, %2};" : "=l"(out2) : "r"(rl_), "r"(rh_));     \
} while (0)

__device__ __forceinline__ void ins5(float t, int idx, float tv[5], int ti[5]) {
    if (t > tv[4]) {
        tv[4] = t; ti[4] = idx;
        #pragma unroll
        for (int s = 4; s > 0; s--) {
            if (tv[s] > tv[s-1]) {
                float a = tv[s]; tv[s] = tv[s-1]; tv[s-1] = a;
                int   b = ti[s]; ti[s] = ti[s-1]; ti[s-1] = b;
            }
        }
    }
}

__global__ void __launch_bounds__(NTH, 2)
attn_kernel(const float* __restrict__ qg_, const float* __restrict__ kg_,
            const float* __restrict__ vg_, float* __restrict__ og_) {
    extern __shared__ float smem[];
    float* ssc = smem;                       // [128][132] score tile + scratch
    float* qsm = smem + SSC_FL;              // [2][CHUNK][128] plain q
    float* ksm = qsm + 2 * QBUF_FL;          // [2][CHUNK][128]

    // grid (128, 8): x = bh (fast), y = qt-rank. Heavy -> light bid order.
    const int bh  = blockIdx.x;
    const int qt  = (gridDim.y - 1) - blockIdx.y;
    const int tid = threadIdx.x;
    const int tr  = tid >> 4;
    const int tc  = tid & 15;

    const float* qg = qg_ + ((size_t)bh * SEQ + (size_t)qt * QT) * DKH;
    const float* kg = kg_ + (size_t)bh * SEQ * DKH;
    const float* vg = vg_ + (size_t)bh * SEQ * DKH;
    float*       og = og_ + ((size_t)bh * SEQ + (size_t)qt * QT) * DKH;

    const int q    = tid & 127;
    const int half = tid >> 7;
    const int row_l = tid & 127;
    const int dq_l  = (tid >> 7) * 4;        // which float4 of the 8-d chunk

    const float tscale = 0.12751743f;        // (1/sqrt(128)) * log2(e)

    const ull kMG   = pk2(12582912.0f, 12582912.0f);
    const ull kNMG  = pk2(-12582912.0f, -12582912.0f);
    const ull kNEG1 = pk2(-1.0f, -1.0f);
    const ull kC5   = pk2(1.3333558e-3f, 1.3333558e-3f);
    const ull kC4   = pk2(9.6181291e-3f, 9.6181291e-3f);
    const ull kC3   = pk2(5.5504109e-2f, 5.5504109e-2f);
    const ull kC2   = pk2(2.4022651e-1f, 2.4022651e-1f);
    const ull kC1   = pk2(6.9314718e-1f, 6.9314718e-1f);
    const ull kC0   = pk2(1.0f, 1.0f);

    float m = -1.0e30f;
    ull Z2a = 0ULL, Z2b = 0ULL;              // packed partial Z accumulators
    ull negm2 = pk2(1.0e30f, 1.0e30f);
    float tv[5]; int tix[5];
    #pragma unroll
    for (int i = 0; i < 5; i++) { tv[i] = SENT; tix[i] = 0; }
    // sf[0..4] lives in (dead-at-scan-time) staging smem for the 5 rec threads
    float* sfp = qsm + q * 8;
    const bool rec = (qt == 0) && (half == 0) && (q < KIDX);

    for (int kt = 0; kt <= qt; kt++) {
        const float* kgt = kg + (size_t)kt * QT * DKH;

        ull acc2[8][4];
        #pragma unroll
        for (int i = 0; i < 8; i++)
            #pragma unroll
            for (int j = 0; j < 4; j++) acc2[i][j] = 0ULL;

        float4 qv, kv;
        qv = *(const float4*)(qg  + (size_t)row_l * DKH + dq_l);
        kv = *(const float4*)(kgt + (size_t)row_l * DKH + dq_l);
        {   float* qd = qsm; float* kd = ksm;
            qd[(dq_l+0)*128 + row_l] = qv.x;
            qd[(dq_l+1)*128 + row_l] = qv.y;
            qd[(dq_l+2)*128 + row_l] = qv.z;
            qd[(dq_l+3)*128 + row_l] = qv.w;
            kd[(dq_l+0)*128 + row_l] = kv.x;
            kd[(dq_l+1)*128 + row_l] = kv.y;
            kd[(dq_l+2)*128 + row_l] = kv.z;
            kd[(dq_l+3)*128 + row_l] = kv.w;
        }
        __syncthreads();

        for (int c = 0; c < NCHUNK; c++) {
            if (c + 1 < NCHUNK) {
                int dbase = (c + 1) * CHUNK;
                qv = *(const float4*)(qg  + (size_t)row_l * DKH + dbase + dq_l);
                kv = *(const float4*)(kgt + (size_t)row_l * DKH + dbase + dq_l);
            }
            const float* qb = qsm + (c & 1) * QBUF_FL;
            const float* kb = ksm + (c & 1) * KBUF_FL;
            #pragma unroll
            for (int d = 0; d < CHUNK; d++) {
                U4 a0, a1, b0, b1;
                a0.f = *(const float4*)(qb + d * 128 + tr * 8);
                a1.f = *(const float4*)(qb + d * 128 + tr * 8 + 4);
                b0.f = *(const float4*)(kb + d * 128 + tc * 8);
                b1.f = *(const float4*)(kb + d * 128 + tc * 8 + 4);
                float av[8] = {a0.f.x, a0.f.y, a0.f.z, a0.f.w,
                               a1.f.x, a1.f.y, a1.f.z, a1.f.w};
                #pragma unroll
                for (int i = 0; i < 8; i++) {
                    ull ad = pk2(av[i], av[i]);
                    acc2[i][0] = fma2v(ad, b0.u[0], acc2[i][0]);
                    acc2[i][1] = fma2v(ad, b0.u[1], acc2[i][1]);
                    acc2[i][2] = fma2v(ad, b1.u[0], acc2[i][2]);
                    acc2[i][3] = fma2v(ad, b1.u[1], acc2[i][3]);
                }
            }
            if (c + 1 < NCHUNK) {
                float* qd = qsm + ((c + 1) & 1) * QBUF_FL;
                float* kd = ksm + ((c + 1) & 1) * KBUF_FL;
                qd[(dq_l+0)*128 + row_l] = qv.x;
                qd[(dq_l+1)*128 + row_l] = qv.y;
                qd[(dq_l+2)*128 + row_l] = qv.z;
                qd[(dq_l+3)*128 + row_l] = qv.w;
                kd[(dq_l+0)*128 + row_l] = kv.x;
                kd[(dq_l+1)*128 + row_l] = kv.y;
                kd[(dq_l+2)*128 + row_l] = kv.z;
                kd[(dq_l+3)*128 + row_l] = kv.w;
                __syncthreads();
            }
        }

        // write score tile in t-space, causal mask on diag tile
        const bool diag = (kt == qt);
        #pragma unroll
        for (int i = 0; i < 8; i++) {
            int qrow = tr * 8 + i;
            float s[8];
            #pragma unroll
            for (int jp = 0; jp < 4; jp++) {
                float lo, hi;
                asm("mov.b64 {%0,%1}, %2;" : "=f"(lo), "=f"(hi) : "l"(acc2[i][jp]));
                s[2*jp]   = lo * tscale;
                s[2*jp+1] = hi * tscale;
            }
            #pragma unroll
            for (int j = 0; j < 8; j++) {
                int kcol = tc * 8 + j;
                if (diag && kcol > qrow) s[j] = TMASK;
            }
            float4* dst = (float4*)(ssc + qrow * SPITCH + tc * 8);
            dst[0] = make_float4(s[0], s[1], s[2], s[3]);
            dst[1] = make_float4(s[4], s[5], s[6], s[7]);
        }
        __syncthreads();

        // scan: 2 threads/row, 64 elems each (fixed 16-group unrolled body).
        // Z kept as two packed f32x2 accumulators -> group-to-group dependency
        // is one packed add, not four serial scalar adds.
        const float* srowf = ssc + q * SPITCH + half * 64;
        const int kb0 = kt * QT + half * 64;
        #pragma unroll 4
        for (int g = 0; g < 16; g++) {
            U4 t4; t4.f = *(const float4*)(srowf + g * 4);
            if (rec && kt == 0) {
                if (g == 0) { sfp[0]=t4.f.x; sfp[1]=t4.f.y; sfp[2]=t4.f.z; sfp[3]=t4.f.w; }
                else if (g == 1) { sfp[4]=t4.f.x; }
            }
            float gm = fmaxf(fmaxf(t4.f.x, t4.f.y), fmaxf(t4.f.z, t4.f.w));
            if (gm > m) {
                float sc = fexp2(m - gm);
                ull sc2 = pk2(sc, sc);
                Z2a = mul2v(Z2a, sc2);
                Z2b = mul2v(Z2b, sc2);
                m = gm;
                negm2 = pk2(-m, -m);
            }
            ull e01, e23;
            PEXP2P(t4.u[0], negm2, e01);
            PEXP2P(t4.u[1], negm2, e23);
            Z2a = add2v(Z2a, e01);
            Z2b = add2v(Z2b, e23);
            if (gm > tv[4]) {
                int kb = kb0 + g * 4;
                ins5(t4.f.x, kb + 0, tv, tix);
                ins5(t4.f.y, kb + 1, tv, tix);
                ins5(t4.f.z, kb + 2, tv, tix);
                ins5(t4.f.w, kb + 3, tv, tix);
            }
        }
        // no sync needed: next tile's staging buffers are disjoint from ssc,
        // and ssc is rewritten only after the chunk-loop barriers
    }

    // fold packed Z to scalar (regrouped sum: perturbs weights ~1e-7, safe)
    float Z;
    {
        float z0, z1, z2, z3;
        asm("mov.b64 {%0,%1}, %2;" : "=f"(z0), "=f"(z1) : "l"(Z2a));
        asm("mov.b64 {%0,%1}, %2;" : "=f"(z2), "=f"(z3) : "l"(Z2b));
        Z = (z0 + z1) + (z2 + z3);
    }

    // inline Sum(v) for qt==0 (only rows 1..4 consume it); qt0 CTAs are in the
    // light tail wave so this extra work is fully absorbed
    if (qt == 0) {
        int d = tid & 127, part = tid >> 7;
        const float* vp = vg + (size_t)part * 512 * DKH + d;
        float s0 = 0.f, s1 = 0.f, s2 = 0.f, s3 = 0.f;
        #pragma unroll 4
        for (int r = 0; r < 512; r += 4) {
            s0 += vp[(size_t)(r+0) * DKH];
            s1 += vp[(size_t)(r+1) * DKH];
            s2 += vp[(size_t)(r+2) * DKH];
            s3 += vp[(size_t)(r+3) * DKH];
        }
        ssc[VSUM_OFF + part * 128 + d] = (s0 + s1) + (s2 + s3);
    }

    __syncthreads();

    // publish half=1 state
    if (half) {
        float* pp = ssc + q * 24;
        pp[0] = m; pp[1] = Z;
        #pragma unroll
        for (int s = 0; s < 5; s++) { pp[2+s] = tv[s]; ((int*)pp)[7+s] = tix[s]; }
    }
    __syncthreads();

    // merge + finalize weights (half=0 threads)
    if (!half) {
        const float* pp = ssc + q * 24;
        float m1 = pp[0], Z1 = pp[1];
        float mm = fmaxf(m, m1);
        float Zm = Z * fexp2(fmaxf(m - mm, -126.0f)) + Z1 * fexp2(fmaxf(m1 - mm, -126.0f));
        #pragma unroll
        for (int s = 0; s < 5; s++) ins5(pp[2+s], ((const int*)pp)[7+s], tv, tix);

        int r = qt * QT + q;
        float wv[5]; int wi[5]; float cu = 0.0f;
        #pragma unroll
        for (int i = 0; i < 5; i++) { wv[i] = 0.0f; wi[i] = 0; }

        if (r >= KIDX) {
            float e[5], D = 0.0f;
            float invZ = 1.0f / Zm;
            #pragma unroll
            for (int i = 0; i < 5; i++) {
                float p = fexp2(tv[i] - mm) * invZ;   // first-softmax prob
                e[i] = __expf(p);
                D += e[i];
            }
            float inv = 1.0f / D;
            #pragma unroll
            for (int i = 0; i < 5; i++) { wv[i] = e[i] * inv; wi[i] = tix[i]; }
        } else if (r >= 1) {
            float D = (float)(SEQ - 1 - r);
            float e[KIDX];
            float invZ = 1.0f / Zm;
            #pragma unroll
            for (int j = 0; j < KIDX; j++) {
                e[j] = 0.0f;
                if (j <= r) {
                    float p = fexp2(sfp[j] - mm) * invZ;
                    e[j] = expm1f(p);                 // e^p - 1
                    D += e[j] + 1.0f;
                }
            }
            float inv = 1.0f / D;
            cu = inv;
            #pragma unroll
            for (int j = 0; j < KIDX; j++) {
                if (j <= r) { wv[j] = e[j] * inv; wi[j] = j; }
            }
        }
        float* fs = ssc + 4096 + q * 12;
        fs[0] = cu;
        #pragma unroll
        for (int i = 0; i < 5; i++) { fs[1+i] = wv[i]; ((int*)fs)[6+i] = wi[i]; }
    }
    __syncthreads();

    // gather epilogue: 2 threads/row, 64 dims each
    {
        const float* fs = ssc + 4096 + q * 12;
        float cu = fs[0];
        float w0 = fs[1], w1 = fs[2], w2 = fs[3], w3 = fs[4], w4 = fs[5];
        const int* ip = (const int*)fs;
        const float4* v0 = (const float4*)(vg + (size_t)ip[6]  * DKH + half * 64);
        const float4* v1 = (const float4*)(vg + (size_t)ip[7]  * DKH + half * 64);
        const float4* v2 = (const float4*)(vg + (size_t)ip[8]  * DKH + half * 64);
        const float4* v3 = (const float4*)(vg + (size_t)ip[9]  * DKH + half * 64);
        const float4* v4 = (const float4*)(vg + (size_t)ip[10] * DKH + half * 64);
        const float4* p0 = (const float4*)(ssc + VSUM_OFF + half * 64);
        const float4* p1 = (const float4*)(ssc + VSUM_OFF + 128 + half * 64);
        float4* op = (float4*)(og + (size_t)q * DKH + half * 64);
        const bool hasvs = (qt == 0);
        #pragma unroll
        for (int d = 0; d < 16; d++) {
            float4 o4 = make_float4(0.f, 0.f, 0.f, 0.f);
            if (hasvs) {
                float4 a0 = p0[d], a1 = p1[d];
                o4.x = cu * (a0.x + a1.x); o4.y = cu * (a0.y + a1.y);
                o4.z = cu * (a0.z + a1.z); o4.w = cu * (a0.w + a1.w);
            }
            float4 b;
            b = v0[d]; o4.x=fmaf(w0,b.x,o4.x); o4.y=fmaf(w0,b.y,o4.y); o4.z=fmaf(w0,b.z,o4.z); o4.w=fmaf(w0,b.w,o4.w);
            b = v1[d]; o4.x=fmaf(w1,b.x,o4.x); o4.y=fmaf(w1,b.y,o4.y); o4.z=fmaf(w1,b.z,o4.z); o4.w=fmaf(w1,b.w,o4.w);
            b = v2[d]; o4.x=fmaf(w2,b.x,o4.x); o4.y=fmaf(w2,b.y,o4.y); o4.z=fmaf(w2,b.z,o4.z); o4.w=fmaf(w2,b.w,o4.w);
            b = v3[d]; o4.x=fmaf(w3,b.x,o4.x); o4.y=fmaf(w3,b.y,o4.y); o4.z=fmaf(w3,b.z,o4.z); o4.w=fmaf(w3,b.w,o4.w);
            b = v4[d]; o4.x=fmaf(w4,b.x,o4.x); o4.y=fmaf(w4,b.y,o4.y); o4.z=fmaf(w4,b.z,o4.z); o4.w=fmaf(w4,b.w,o4.w);
            op[d] = o4;
        }
    }
}

extern "C" void kernel_launch(void* const* d_in, const int* in_sizes, int n_in,
                              void* d_out, int out_size) {
    const float* q = (const float*)d_in[0];
    const float* k = (const float*)d_in[1];
    const float* v = (const float*)d_in[2];
    float* o = (float*)d_out;
    cudaFuncSetAttribute(attn_kernel, cudaFuncAttributeMaxDynamicSharedMemorySize, SMEMSZ);
    attn_kernel<<<dim3(128, 8), NTH, SMEMSZ>>>(q, k, v, o);
}